// round 1
// baseline (speedup 1.0000x reference)
#include <cuda_runtime.h>
#include <math.h>

// Problem: out = mean_b ||y_pred[b,:] - y_true[b,:]||_2
// B=64, T=524288, fp32. Pure HBM streaming reduction.

#define B_ROWS 64
#define T_LEN 524288
#define BLOCKS_PER_ROW 32
#define CHUNK (T_LEN / BLOCKS_PER_ROW)   // 16384 elems
#define THREADS 256
#define VEC_PER_THREAD (CHUNK / (THREADS * 4))  // 16 float4 per thread

// Scratch for per-block partial sums (allocation-free rule -> __device__ global)
__device__ float g_partials[B_ROWS * BLOCKS_PER_ROW];

__global__ __launch_bounds__(THREADS)
void sqdiff_partial_kernel(const float* __restrict__ y_pred,
                           const float* __restrict__ y_true) {
    const int block = blockIdx.x;
    const int row = block / BLOCKS_PER_ROW;
    const int chunk = block % BLOCKS_PER_ROW;
    const long long base = (long long)row * T_LEN + (long long)chunk * CHUNK;

    const float4* p4 = reinterpret_cast<const float4*>(y_pred + base);
    const float4* t4 = reinterpret_cast<const float4*>(y_true + base);

    float acc = 0.0f;
#pragma unroll
    for (int i = 0; i < VEC_PER_THREAD; i++) {
        const int idx = i * THREADS + threadIdx.x;
        float4 a = __ldg(&p4[idx]);
        float4 b = __ldg(&t4[idx]);
        float d0 = a.x - b.x;
        float d1 = a.y - b.y;
        float d2 = a.z - b.z;
        float d3 = a.w - b.w;
        acc = fmaf(d0, d0, acc);
        acc = fmaf(d1, d1, acc);
        acc = fmaf(d2, d2, acc);
        acc = fmaf(d3, d3, acc);
    }

    // Block reduce: warp shuffle, then shared across 8 warps
    const int lane = threadIdx.x & 31;
    const int wid = threadIdx.x >> 5;
#pragma unroll
    for (int off = 16; off > 0; off >>= 1)
        acc += __shfl_xor_sync(0xFFFFFFFFu, acc, off);

    __shared__ float warp_sums[THREADS / 32];
    if (lane == 0) warp_sums[wid] = acc;
    __syncthreads();

    if (wid == 0) {
        float v = (lane < THREADS / 32) ? warp_sums[lane] : 0.0f;
#pragma unroll
        for (int off = 4; off > 0; off >>= 1)
            v += __shfl_xor_sync(0xFFFFFFFFu, v, off);
        if (lane == 0)
            g_partials[block] = v;
    }
}

__global__ __launch_bounds__(64)
void finalize_kernel(float* __restrict__ out) {
    const int t = threadIdx.x;  // 64 threads, one per row
    double s = 0.0;
#pragma unroll
    for (int i = 0; i < BLOCKS_PER_ROW; i++)
        s += (double)g_partials[t * BLOCKS_PER_ROW + i];
    double r = sqrt(s);

    __shared__ double sh[64];
    sh[t] = r;
    __syncthreads();
#pragma unroll
    for (int off = 32; off > 0; off >>= 1) {
        if (t < off) sh[t] += sh[t + off];
        __syncthreads();
    }
    if (t == 0)
        out[0] = (float)(sh[0] / (double)B_ROWS);
}

extern "C" void kernel_launch(void* const* d_in, const int* in_sizes, int n_in,
                              void* d_out, int out_size) {
    const float* y_pred = (const float*)d_in[0];
    const float* y_true = (const float*)d_in[1];
    float* out = (float*)d_out;

    sqdiff_partial_kernel<<<B_ROWS * BLOCKS_PER_ROW, THREADS>>>(y_pred, y_true);
    finalize_kernel<<<1, 64>>>(out);
}